// round 8
// baseline (speedup 1.0000x reference)
#include <cuda_runtime.h>

// Problem constants
#define B     256
#define NSRC  100
#define D4    192          // 768 / 4 (float4 units per embedding)
#define R     80
#define RP1   81

// Output layout (float element offsets), tuple order:
// vis_packed (B,R,768), txt_packed (B,R,768), text_mask (B,81),
// img_mask (B,81), rr_mod (B,80), labels (B,80)
#define TXT_OFF    (B*R*768)
#define TMASK_OFF  (2*B*R*768)
#define IMASK_OFF  (TMASK_OFF + B*RP1)
#define RRMOD_OFF  (IMASK_OFF + B*RP1)
#define LAB_OFF    (RRMOD_OFF + B*R)
#define TXT4_OFF   (TXT_OFF / 4)

#define SLOTS_PER_BLK 4    // R/4 = 20 blocks per row -> 5120 blocks (fine tail)

// Fused kernel: grid (R/4, B), 192 threads.
// Warp 0 rebuilds the stable compaction map for row b via ballots (rr row is
// L2-resident); then all threads stream 4 slots x {vis,txt}.
__global__ __launch_bounds__(192) void fused_kernel(
    const float4* __restrict__ vis,
    const float4* __restrict__ txt,
    const float*  __restrict__ labels_in,
    const float*  __restrict__ rrcp,
    float* __restrict__ out)
{
    const int b = blockIdx.y;
    const int t = threadIdx.x;

    __shared__ int s_map[R];    // dest slot -> src slot (-1 = zeros)
    __shared__ int s_count;
    __shared__ int s_anynz;

    if (t < 32) {
        #pragma unroll
        for (int c = 0; c < 3; ++c) {
            int j = c * 32 + t;
            if (j < R) s_map[j] = -1;
        }
        __syncwarp();

        const unsigned lt = (1u << t) - 1u;
        int base = 0;
        bool anynz = false;
        #pragma unroll
        for (int c = 0; c < 3; ++c) {
            int j = c * 32 + t;
            float rr = (j < R) ? rrcp[b * NSRC + j] : 0.0f;
            unsigned selm = __ballot_sync(0xFFFFFFFFu, (j < R) && (rr > 0.5f));
            if ((j < R) && (rr > 0.5f))
                s_map[base + __popc(selm & lt)] = j;
            anynz |= (j < R) && (rr >= 0.5f);
            base += __popc(selm);
        }
        unsigned nzm = __ballot_sync(0xFFFFFFFFu, anynz);
        if (t == 0) {
            s_count = base;
            s_anynz = (nzm != 0u);
        }
    }
    __syncthreads();

    // Small per-row outputs (one block per row does them)
    if (blockIdx.x == 0) {
        const int count = s_count;
        if (t < R) {
            float rr = rrcp[b * NSRC + t];
            float rm = (rr < 0.5f) ? 0.0f : rr;
            if (t == 0 && !s_anynz) rm = 1.0f;       // zero-row fix
            out[RRMOD_OFF + b * R + t] = rm;
            out[LAB_OFF + b * R + t]   = labels_in[b * NSRC + t];
        }
        if (t < RP1) {
            float tm = (t <= count) ? 1.0f : 0.0f;
            out[TMASK_OFF + b * RP1 + t] = tm;
            out[IMASK_OFF + b * RP1 + t] = (b == B - 1) ? tm : 1.0f;
        }
    }

    // Bulk gather: 4 slots, both halves, column = t. No div/mod.
    const int slot0 = blockIdx.x * SLOTS_PER_BLK;
    const float4 zero = make_float4(0.0f, 0.0f, 0.0f, 0.0f);
    const float4* __restrict__ vbase = vis + (size_t)b * NSRC * D4 + t;
    const float4* __restrict__ tbase = txt + (size_t)b * NSRC * D4 + t;
    float4* __restrict__ ov = (float4*)out + (size_t)(b * R + slot0) * D4 + t;
    float4* __restrict__ ot = (float4*)out + TXT4_OFF + (size_t)(b * R + slot0) * D4 + t;

    const int s0 = s_map[slot0 + 0];
    const int s1 = s_map[slot0 + 1];
    const int s2 = s_map[slot0 + 2];
    const int s3 = s_map[slot0 + 3];
    // front-batch 8 independent loads (L2-resident across graph replays)
    float4 v0 = (s0 >= 0) ? __ldg(vbase + s0 * D4) : zero;
    float4 v1 = (s1 >= 0) ? __ldg(vbase + s1 * D4) : zero;
    float4 v2 = (s2 >= 0) ? __ldg(vbase + s2 * D4) : zero;
    float4 v3 = (s3 >= 0) ? __ldg(vbase + s3 * D4) : zero;
    float4 x0 = (s0 >= 0) ? __ldg(tbase + s0 * D4) : zero;
    float4 x1 = (s1 >= 0) ? __ldg(tbase + s1 * D4) : zero;
    float4 x2 = (s2 >= 0) ? __ldg(tbase + s2 * D4) : zero;
    float4 x3 = (s3 >= 0) ? __ldg(tbase + s3 * D4) : zero;
    ov[0 * D4] = v0;
    ov[1 * D4] = v1;
    ov[2 * D4] = v2;
    ov[3 * D4] = v3;
    ot[0 * D4] = x0;
    ot[1 * D4] = x1;
    ot[2 * D4] = x2;
    ot[3 * D4] = x3;
}

extern "C" void kernel_launch(void* const* d_in, const int* in_sizes, int n_in,
                              void* d_out, int out_size) {
    // 0: mean_pooling_vec (unused)  1: merge_text_vec (unused)
    // 2: vis (B,N,1,D)  3: txt (B,N,1,D)  4: labels (B,N)  5: RRCP (B,N)
    const float4* vis = (const float4*)d_in[2];
    const float4* txt = (const float4*)d_in[3];
    const float*  lab = (const float*)d_in[4];
    const float*  rr  = (const float*)d_in[5];
    float* out = (float*)d_out;

    fused_kernel<<<dim3(R / SLOTS_PER_BLK, B), 192>>>(vis, txt, lab, rr, out);
}

// round 13
// speedup vs baseline: 1.0193x; 1.0193x over previous
#include <cuda_runtime.h>

// Problem constants
#define B     256
#define NSRC  100
#define C32   96           // 768 floats = 96 x 32-byte chunks per embedding
#define R     80
#define RP1   81

// Output layout (float element offsets), tuple order:
// vis_packed (B,R,768), txt_packed (B,R,768), text_mask (B,81),
// img_mask (B,81), rr_mod (B,80), labels (B,80)
#define TXT_OFF    (B*R*768)
#define TMASK_OFF  (2*B*R*768)
#define IMASK_OFF  (TMASK_OFF + B*RP1)
#define RRMOD_OFF  (IMASK_OFF + B*RP1)
#define LAB_OFF    (RRMOD_OFF + B*R)
#define TXT32_OFF  (TXT_OFF / 8)     // in 32-byte (ulonglong4) units

#define SLOTS_PER_BLK 4    // R/4 = 20 blocks per row -> 5120 blocks

// 256-bit L2 evict_last read: keep the 63MB input set sticky in L2.
__device__ __forceinline__ ulonglong4 ldg256_evict_last(const ulonglong4* p) {
    ulonglong4 v;
    asm volatile("ld.global.nc.L2::evict_last.v4.b64 {%0,%1,%2,%3}, [%4];"
                 : "=l"(v.x), "=l"(v.y), "=l"(v.z), "=l"(v.w)
                 : "l"(p));
    return v;
}

// 256-bit L2 evict_first store: output stream recycles its own L2 lines.
__device__ __forceinline__ void stg256_evict_first(ulonglong4* p, ulonglong4 v) {
    asm volatile("st.global.L2::evict_first.v4.b64 [%0], {%1,%2,%3,%4};"
                 :: "l"(p), "l"(v.x), "l"(v.y), "l"(v.z), "l"(v.w)
                 : "memory");
}

// Fused kernel: grid (R/4, B), 192 threads (2 subgroups of 96 lanes).
// Warp 0 rebuilds the stable compaction map for row b via ballots; then each
// thread streams chunk c of 2 slots x {vis,txt} with 256-bit accesses and
// L2-residency hints.
__global__ __launch_bounds__(192) void fused_kernel(
    const ulonglong4* __restrict__ vis,
    const ulonglong4* __restrict__ txt,
    const float*  __restrict__ labels_in,
    const float*  __restrict__ rrcp,
    float* __restrict__ out)
{
    const int b = blockIdx.y;
    const int t = threadIdx.x;

    __shared__ int s_map[R];    // dest slot -> src slot (-1 = zeros)
    __shared__ int s_count;
    __shared__ int s_anynz;

    if (t < 32) {
        #pragma unroll
        for (int c = 0; c < 3; ++c) {
            int j = c * 32 + t;
            if (j < R) s_map[j] = -1;
        }
        __syncwarp();

        const unsigned lt = (1u << t) - 1u;
        int base = 0;
        bool anynz = false;
        #pragma unroll
        for (int c = 0; c < 3; ++c) {
            int j = c * 32 + t;
            float rr = (j < R) ? rrcp[b * NSRC + j] : 0.0f;
            unsigned selm = __ballot_sync(0xFFFFFFFFu, (j < R) && (rr > 0.5f));
            if ((j < R) && (rr > 0.5f))
                s_map[base + __popc(selm & lt)] = j;
            anynz |= (j < R) && (rr >= 0.5f);
            base += __popc(selm);
        }
        unsigned nzm = __ballot_sync(0xFFFFFFFFu, anynz);
        if (t == 0) {
            s_count = base;
            s_anynz = (nzm != 0u);
        }
    }
    __syncthreads();

    // Small per-row outputs (one block per row does them)
    if (blockIdx.x == 0) {
        const int count = s_count;
        if (t < R) {
            float rr = rrcp[b * NSRC + t];
            float rm = (rr < 0.5f) ? 0.0f : rr;
            if (t == 0 && !s_anynz) rm = 1.0f;       // zero-row fix
            out[RRMOD_OFF + b * R + t] = rm;
            out[LAB_OFF + b * R + t]   = labels_in[b * NSRC + t];
        }
        if (t < RP1) {
            float tm = (t <= count) ? 1.0f : 0.0f;
            out[TMASK_OFF + b * RP1 + t] = tm;
            out[IMASK_OFF + b * RP1 + t] = (b == B - 1) ? tm : 1.0f;
        }
    }

    // Bulk gather in 32-byte chunks.
    // t -> chunk c = t % 96, sub = t / 96; this thread serves dest slots
    // slot0+sub and slot0+sub+2 for both vis and txt.
    const int c   = t % C32;
    const int sub = t / C32;
    const int slotA = blockIdx.x * SLOTS_PER_BLK + sub;
    const int slotB = slotA + 2;

    const int sA = s_map[slotA];
    const int sB = s_map[slotB];

    const ulonglong4 zero = make_ulonglong4(0ull, 0ull, 0ull, 0ull);
    const ulonglong4* __restrict__ vrow = vis + (size_t)b * NSRC * C32 + c;
    const ulonglong4* __restrict__ trow = txt + (size_t)b * NSRC * C32 + c;
    ulonglong4* __restrict__ o32 = (ulonglong4*)out;

    // front-batch 4 independent 32B sticky loads
    ulonglong4 va = (sA >= 0) ? ldg256_evict_last(vrow + sA * C32) : zero;
    ulonglong4 vb = (sB >= 0) ? ldg256_evict_last(vrow + sB * C32) : zero;
    ulonglong4 xa = (sA >= 0) ? ldg256_evict_last(trow + sA * C32) : zero;
    ulonglong4 xb = (sB >= 0) ? ldg256_evict_last(trow + sB * C32) : zero;

    stg256_evict_first(o32 + (size_t)(b * R + slotA) * C32 + c, va);
    stg256_evict_first(o32 + (size_t)(b * R + slotB) * C32 + c, vb);
    stg256_evict_first(o32 + TXT32_OFF + (size_t)(b * R + slotA) * C32 + c, xa);
    stg256_evict_first(o32 + TXT32_OFF + (size_t)(b * R + slotB) * C32 + c, xb);
}

extern "C" void kernel_launch(void* const* d_in, const int* in_sizes, int n_in,
                              void* d_out, int out_size) {
    // 0: mean_pooling_vec (unused)  1: merge_text_vec (unused)
    // 2: vis (B,N,1,D)  3: txt (B,N,1,D)  4: labels (B,N)  5: RRCP (B,N)
    const ulonglong4* vis = (const ulonglong4*)d_in[2];
    const ulonglong4* txt = (const ulonglong4*)d_in[3];
    const float*  lab = (const float*)d_in[4];
    const float*  rr  = (const float*)d_in[5];
    float* out = (float*)d_out;

    fused_kernel<<<dim3(R / SLOTS_PER_BLK, B), 192>>>(vis, txt, lab, rr, out);
}